// round 4
// baseline (speedup 1.0000x reference)
#include <cuda_runtime.h>
#include <math.h>

#define YAT_EPS (1.0f/137.0f)

// ---------------- scratch (allocation-free rule: __device__ globals) ----------
static __device__ float g_qkv[4096u*2304u];   // [B*T, 3C]
static __device__ float g_att[4096u*768u];    // [B*T, C]  (already [B,T,H,D])
static __device__ float g_xnorm[4096];
static __device__ float g_onorm[4096];
static __device__ float g_wn1[2304];
static __device__ float g_wn2[768];

// ---------------- norms -------------------------------------------------------
__global__ void col_sqnorm(const float* __restrict__ W, float* __restrict__ out,
                           int K, int N) {
    int col = blockIdx.x * blockDim.x + threadIdx.x;
    if (col >= N) return;
    float s = 0.f;
    for (int k = 0; k < K; k++) { float v = W[(size_t)k * N + col]; s += v * v; }
    out[col] = s;
}

__global__ void row_sqnorm(const float* __restrict__ X, float* __restrict__ out,
                           int cols) {
    int row = blockIdx.x;
    const float* p = X + (size_t)row * cols;
    float s = 0.f;
    for (int c = threadIdx.x; c < cols; c += blockDim.x) { float v = p[c]; s += v * v; }
    #pragma unroll
    for (int o = 16; o; o >>= 1) s += __shfl_down_sync(0xffffffffu, s, o);
    __shared__ float ws[8];
    if ((threadIdx.x & 31) == 0) ws[threadIdx.x >> 5] = s;
    __syncthreads();
    if (threadIdx.x == 0) {
        float t = 0.f;
        int nw = blockDim.x >> 5;
        for (int i = 0; i < nw; i++) t += ws[i];
        out[row] = t;
    }
}

// ---------------- yat GEMM: C = yat(A @ B) ------------------------------------
// 64x64 tile, BK=16, 256 threads, 4x4 per thread.
__global__ void yat_gemm(const float* __restrict__ A, const float* __restrict__ B,
                         const float* __restrict__ rown, const float* __restrict__ coln,
                         const float* __restrict__ bias, const float* __restrict__ alpha,
                         float* __restrict__ C, int M, int N, int K, float base) {
    __shared__ float As[16 * 64];   // [k][r]
    __shared__ float Bs[16 * 64];   // [k][c]
    int tid = threadIdx.x;
    int tx = tid & 15, ty = tid >> 4;
    int m0 = blockIdx.y * 64, n0 = blockIdx.x * 64;

    float acc[4][4] = {};
    for (int kt = 0; kt < K; kt += 16) {
        {
            int r = tid >> 2, kq = tid & 3;
            float4 va = *(const float4*)(A + (size_t)(m0 + r) * K + kt + kq * 4);
            As[(kq * 4 + 0) * 64 + r] = va.x;
            As[(kq * 4 + 1) * 64 + r] = va.y;
            As[(kq * 4 + 2) * 64 + r] = va.z;
            As[(kq * 4 + 3) * 64 + r] = va.w;
            int kb = tid >> 4, cq = tid & 15;
            float4 vb = *(const float4*)(B + (size_t)(kt + kb) * N + n0 + cq * 4);
            *(float4*)&Bs[kb * 64 + cq * 4] = vb;
        }
        __syncthreads();
        #pragma unroll
        for (int kk = 0; kk < 16; kk++) {
            float4 a4 = *(const float4*)&As[kk * 64 + ty * 4];
            float4 b4 = *(const float4*)&Bs[kk * 64 + tx * 4];
            float av[4] = {a4.x, a4.y, a4.z, a4.w};
            float bv[4] = {b4.x, b4.y, b4.z, b4.w};
            #pragma unroll
            for (int i = 0; i < 4; i++)
                #pragma unroll
                for (int j = 0; j < 4; j++)
                    acc[i][j] = fmaf(av[i], bv[j], acc[i][j]);
        }
        __syncthreads();
    }

    float sc = powf(base, alpha[0]);
    #pragma unroll
    for (int i = 0; i < 4; i++) {
        int row = m0 + ty * 4 + i;
        float rn = rown[row];
        #pragma unroll
        for (int j = 0; j < 4; j++) {
            int col = n0 + tx * 4 + j;
            float dot = acc[i][j];
            float dist = rn + coln[col] - 2.f * dot + YAT_EPS;
            float y = dot * dot / dist + bias[col];
            C[(size_t)row * N + col] = y * sc;
        }
    }
}

// ---------------- yat attention (flash-style, causal) -------------------------
#define ALDS 68
__global__ void yat_attention(const float* __restrict__ qkv, float* __restrict__ att) {
    extern __shared__ float sm[];
    float* Qs   = sm;                // [64][ALDS] row-major  [r][d]
    float* KP   = Qs + 64 * ALDS;    // K as [d][c]; later P as [r][c]
    float* Vs   = KP + 64 * ALDS;    // [c][d]
    float* qn   = Vs + 64 * ALDS;    // 64
    float* kn   = qn + 64;
    float* mrow = kn + 64;
    float* lrow = mrow + 64;
    float* corr = lrow + 64;
    float* red  = corr + 64;         // [64][17]

    int qt = blockIdx.x, h = blockIdx.y, b = blockIdx.z;
    int tid = threadIdx.x;
    int tx = tid & 15, ty = tid >> 4;
    int q0 = qt * 64;
    const float isc = 0.125f;        // 1/sqrt(64)

    size_t baseQ = ((size_t)(b * 1024 + q0)) * 2304 + h * 64;
    for (int e = tid; e < 1024; e += 256) {
        int r = e >> 4, cq = e & 15;
        float4 v = *(const float4*)(qkv + baseQ + (size_t)r * 2304 + cq * 4);
        *(float4*)&Qs[r * ALDS + cq * 4] = v;
    }
    __syncthreads();
    if (tid < 64) {
        float s = 0.f;
        for (int d = 0; d < 64; d++) { float v = Qs[tid * ALDS + d]; s += v * v; }
        qn[tid] = s;
        mrow[tid] = -3.0e38f;
        lrow[tid] = 0.f;
    }

    float o[4][4] = {};
    for (int kt = 0; kt <= qt; kt++) {
        __syncthreads();   // protect prev-iter KP/Vs reads + init
        int k0 = kt * 64;
        size_t baseK = ((size_t)(b * 1024 + k0)) * 2304 + 768 + h * 64;
        for (int e = tid; e < 1024; e += 256) {
            int c = e >> 4, dq = e & 15;
            float4 v = *(const float4*)(qkv + baseK + (size_t)c * 2304 + dq * 4);
            KP[(dq * 4 + 0) * ALDS + c] = v.x;
            KP[(dq * 4 + 1) * ALDS + c] = v.y;
            KP[(dq * 4 + 2) * ALDS + c] = v.z;
            KP[(dq * 4 + 3) * ALDS + c] = v.w;
            float4 w = *(const float4*)(qkv + baseK + 768 + (size_t)c * 2304 + dq * 4);
            *(float4*)&Vs[c * ALDS + dq * 4] = w;
        }
        __syncthreads();
        if (tid < 64) {
            float s = 0.f;
            for (int d = 0; d < 64; d++) { float v = KP[d * ALDS + tid]; s += v * v; }
            kn[tid] = s;
        }
        __syncthreads();

        // S = Q @ K^T  (KP is [d][c])
        float sacc[4][4] = {};
        #pragma unroll 8
        for (int d = 0; d < 64; d++) {
            float av[4], bv[4];
            #pragma unroll
            for (int i = 0; i < 4; i++) av[i] = Qs[(ty * 4 + i) * ALDS + d];
            #pragma unroll
            for (int j = 0; j < 4; j++) bv[j] = KP[d * ALDS + tx * 4 + j];
            #pragma unroll
            for (int i = 0; i < 4; i++)
                #pragma unroll
                for (int j = 0; j < 4; j++)
                    sacc[i][j] = fmaf(av[i], bv[j], sacc[i][j]);
        }

        // yat transform + causal mask + local row max
        float lmax[4] = {-3.0e38f, -3.0e38f, -3.0e38f, -3.0e38f};
        #pragma unroll
        for (int i = 0; i < 4; i++) {
            int r = ty * 4 + i;
            int gq = q0 + r;
            float qnr = qn[r];
            #pragma unroll
            for (int j = 0; j < 4; j++) {
                int c = tx * 4 + j;
                int gk = k0 + c;
                float ds = sacc[i][j] * isc;
                float dist = qnr + kn[c] - 2.f * ds + YAT_EPS;
                float val = ds * ds / dist;
                if (gk > gq) val = -3.0e38f;
                sacc[i][j] = val;
                lmax[i] = fmaxf(lmax[i], val);
            }
        }
        #pragma unroll
        for (int i = 0; i < 4; i++) red[(ty * 4 + i) * 17 + tx] = lmax[i];
        __syncthreads();                      // sync A
        if (tid < 64) {
            float mx = red[tid * 17];
            for (int t = 1; t < 16; t++) mx = fmaxf(mx, red[tid * 17 + t]);
            float mold = mrow[tid];
            float mnew = fmaxf(mold, mx);
            corr[tid] = __expf(mold - mnew);
            mrow[tid] = mnew;
        }
        __syncthreads();                      // sync B

        float lsum[4] = {};
        #pragma unroll
        for (int i = 0; i < 4; i++) {
            float m = mrow[ty * 4 + i];
            #pragma unroll
            for (int j = 0; j < 4; j++) {
                float p = __expf(sacc[i][j] - m);
                sacc[i][j] = p;
                lsum[i] += p;
            }
        }
        // P overwrites K buffer (K reads all done before sync A)
        #pragma unroll
        for (int i = 0; i < 4; i++) {
            #pragma unroll
            for (int j = 0; j < 4; j++)
                KP[(ty * 4 + i) * ALDS + tx * 4 + j] = sacc[i][j];
            red[(ty * 4 + i) * 17 + tx] = lsum[i];
        }
        __syncthreads();                      // sync C
        if (tid < 64) {
            float s = 0.f;
            for (int t = 0; t < 16; t++) s += red[tid * 17 + t];
            lrow[tid] = lrow[tid] * corr[tid] + s;
        }
        float cr[4];
        #pragma unroll
        for (int i = 0; i < 4; i++) cr[i] = corr[ty * 4 + i];
        #pragma unroll
        for (int i = 0; i < 4; i++)
            #pragma unroll
            for (int j = 0; j < 4; j++) o[i][j] *= cr[i];

        // O += P @ V
        #pragma unroll 4
        for (int kv = 0; kv < 64; kv++) {
            float av[4], bv[4];
            #pragma unroll
            for (int i = 0; i < 4; i++) av[i] = KP[(ty * 4 + i) * ALDS + kv];
            #pragma unroll
            for (int j = 0; j < 4; j++) bv[j] = Vs[kv * ALDS + tx * 4 + j];
            #pragma unroll
            for (int i = 0; i < 4; i++)
                #pragma unroll
                for (int j = 0; j < 4; j++)
                    o[i][j] = fmaf(av[i], bv[j], o[i][j]);
        }
    }
    __syncthreads();
    #pragma unroll
    for (int i = 0; i < 4; i++) {
        int r = ty * 4 + i;
        int gq = q0 + r;
        float inv_l = 1.f / lrow[r];
        #pragma unroll
        for (int j = 0; j < 4; j++)
            att[((size_t)(b * 1024 + gq)) * 768 + h * 64 + tx * 4 + j] = o[i][j] * inv_l;
    }
}

// ---------------- launch ------------------------------------------------------
extern "C" void kernel_launch(void* const* d_in, const int* in_sizes, int n_in,
                              void* d_out, int out_size) {
    const float* x          = (const float*)d_in[0];
    // d_in[1] = mask (causal tril, recomputed on device)
    const float* W_attn     = (const float*)d_in[2];
    const float* b_attn     = (const float*)d_in[3];
    const float* alpha_attn = (const float*)d_in[4];
    const float* W_proj     = (const float*)d_in[5];
    const float* b_proj     = (const float*)d_in[6];
    const float* alpha_proj = (const float*)d_in[7];
    float* out = (float*)d_out;

    float *qkv, *att, *xnorm, *onorm, *wn1, *wn2;
    cudaGetSymbolAddress((void**)&qkv,   g_qkv);
    cudaGetSymbolAddress((void**)&att,   g_att);
    cudaGetSymbolAddress((void**)&xnorm, g_xnorm);
    cudaGetSymbolAddress((void**)&onorm, g_onorm);
    cudaGetSymbolAddress((void**)&wn1,   g_wn1);
    cudaGetSymbolAddress((void**)&wn2,   g_wn2);

    const int M = 4096, C = 768, F1 = 2304;
    float base1 = sqrtf((float)F1) / log1pf((float)F1);
    float base2 = sqrtf((float)C)  / log1pf((float)C);

    // norms
    col_sqnorm<<<(F1 + 255) / 256, 256>>>(W_attn, wn1, C, F1);
    col_sqnorm<<<(C  + 255) / 256, 256>>>(W_proj, wn2, C, C);
    row_sqnorm<<<M, 256>>>(x, xnorm, C);

    // QKV = yat_dense(x, W_attn)
    yat_gemm<<<dim3(F1 / 64, M / 64), 256>>>(x, W_attn, xnorm, wn1, b_attn,
                                             alpha_attn, qkv, M, F1, C, base1);

    // attention
    static int smem_set = 0;
    int att_smem = (3 * 64 * ALDS + 5 * 64 + 64 * 17) * (int)sizeof(float);
    if (!smem_set) {
        cudaFuncSetAttribute(yat_attention,
                             cudaFuncAttributeMaxDynamicSharedMemorySize, att_smem);
        smem_set = 1;
    }
    yat_attention<<<dim3(16, 12, 4), 256, att_smem>>>(qkv, att);

    // proj = yat_dense(att, W_proj)
    row_sqnorm<<<M, 256>>>(att, onorm, C);
    yat_gemm<<<dim3(C / 64, M / 64), 256>>>(att, W_proj, onorm, wn2, b_proj,
                                            alpha_proj, out, M, C, C, base2);
}

// round 5
// speedup vs baseline: 1.0100x; 1.0100x over previous
#include <cuda_runtime.h>
#include <math.h>

#define YAT_EPS (1.0f/137.0f)

// ---------------- scratch (allocation-free rule: __device__ globals) ----------
static __device__ float g_qkv[4096u*2304u];   // [B*T, 3C]
static __device__ float g_att[4096u*768u];    // [B*T, C]  (already [B,T,H,D])
static __device__ float g_xnorm[4096];
static __device__ float g_onorm[4096];
static __device__ float g_wn1[2304];
static __device__ float g_wn2[768];

// ---------------- norms -------------------------------------------------------
__global__ void col_sqnorm(const float* __restrict__ W, float* __restrict__ out,
                           int K, int N) {
    int col = blockIdx.x * blockDim.x + threadIdx.x;
    if (col >= N) return;
    float s = 0.f;
    for (int k = 0; k < K; k++) { float v = W[(size_t)k * N + col]; s += v * v; }
    out[col] = s;
}

__global__ void row_sqnorm(const float* __restrict__ X, float* __restrict__ out,
                           int cols) {
    int row = blockIdx.x;
    const float* p = X + (size_t)row * cols;
    float s = 0.f;
    for (int c = threadIdx.x; c < cols; c += blockDim.x) { float v = p[c]; s += v * v; }
    #pragma unroll
    for (int o = 16; o; o >>= 1) s += __shfl_down_sync(0xffffffffu, s, o);
    __shared__ float ws[8];
    if ((threadIdx.x & 31) == 0) ws[threadIdx.x >> 5] = s;
    __syncthreads();
    if (threadIdx.x == 0) {
        float t = 0.f;
        int nw = blockDim.x >> 5;
        for (int i = 0; i < nw; i++) t += ws[i];
        out[row] = t;
    }
}

// ---------------- yat GEMM: C = yat(A @ B) ------------------------------------
// 64x64 tile, BK=16, 256 threads, 4x4 per thread.
__global__ void yat_gemm(const float* __restrict__ A, const float* __restrict__ B,
                         const float* __restrict__ rown, const float* __restrict__ coln,
                         const float* __restrict__ bias, const float* __restrict__ alpha,
                         float* __restrict__ C, int M, int N, int K, float base) {
    __shared__ float As[16 * 64];   // [k][r]
    __shared__ float Bs[16 * 64];   // [k][c]
    int tid = threadIdx.x;
    int tx = tid & 15, ty = tid >> 4;
    int m0 = blockIdx.y * 64, n0 = blockIdx.x * 64;

    float acc[4][4] = {};
    for (int kt = 0; kt < K; kt += 16) {
        {
            int r = tid >> 2, kq = tid & 3;
            float4 va = *(const float4*)(A + (size_t)(m0 + r) * K + kt + kq * 4);
            As[(kq * 4 + 0) * 64 + r] = va.x;
            As[(kq * 4 + 1) * 64 + r] = va.y;
            As[(kq * 4 + 2) * 64 + r] = va.z;
            As[(kq * 4 + 3) * 64 + r] = va.w;
            int kb = tid >> 4, cq = tid & 15;
            float4 vb = *(const float4*)(B + (size_t)(kt + kb) * N + n0 + cq * 4);
            *(float4*)&Bs[kb * 64 + cq * 4] = vb;
        }
        __syncthreads();
        #pragma unroll
        for (int kk = 0; kk < 16; kk++) {
            float4 a4 = *(const float4*)&As[kk * 64 + ty * 4];
            float4 b4 = *(const float4*)&Bs[kk * 64 + tx * 4];
            float av[4] = {a4.x, a4.y, a4.z, a4.w};
            float bv[4] = {b4.x, b4.y, b4.z, b4.w};
            #pragma unroll
            for (int i = 0; i < 4; i++)
                #pragma unroll
                for (int j = 0; j < 4; j++)
                    acc[i][j] = fmaf(av[i], bv[j], acc[i][j]);
        }
        __syncthreads();
    }

    float sc = powf(base, alpha[0]);
    #pragma unroll
    for (int i = 0; i < 4; i++) {
        int row = m0 + ty * 4 + i;
        float rn = rown[row];
        #pragma unroll
        for (int j = 0; j < 4; j++) {
            int col = n0 + tx * 4 + j;
            float dot = acc[i][j];
            float dist = rn + coln[col] - 2.f * dot + YAT_EPS;
            float y = dot * dot / dist + bias[col];
            C[(size_t)row * N + col] = y * sc;
        }
    }
}

// ---------------- yat attention (flash-style, causal) -------------------------
#define ALDS 68
__global__ void yat_attention(const float* __restrict__ qkv, float* __restrict__ att) {
    extern __shared__ float sm[];
    float* Qs   = sm;                // [64][ALDS] row-major  [r][d]
    float* KP   = Qs + 64 * ALDS;    // K as [d][c]; later P as [r][c]
    float* Vs   = KP + 64 * ALDS;    // [c][d]
    float* qn   = Vs + 64 * ALDS;    // 64
    float* kn   = qn + 64;
    float* mrow = kn + 64;
    float* lrow = mrow + 64;
    float* corr = lrow + 64;
    float* red  = corr + 64;         // [64][17]

    int qt = blockIdx.x, h = blockIdx.y, b = blockIdx.z;
    int tid = threadIdx.x;
    int tx = tid & 15, ty = tid >> 4;
    int q0 = qt * 64;
    const float isc = 0.125f;        // 1/sqrt(64)

    size_t baseQ = ((size_t)(b * 1024 + q0)) * 2304 + h * 64;
    for (int e = tid; e < 1024; e += 256) {
        int r = e >> 4, cq = e & 15;
        float4 v = *(const float4*)(qkv + baseQ + (size_t)r * 2304 + cq * 4);
        *(float4*)&Qs[r * ALDS + cq * 4] = v;
    }
    __syncthreads();
    if (tid < 64) {
        float s = 0.f;
        for (int d = 0; d < 64; d++) { float v = Qs[tid * ALDS + d]; s += v * v; }
        qn[tid] = s;
        mrow[tid] = -3.0e38f;
        lrow[tid] = 0.f;
    }

    float o[4][4] = {};
    for (int kt = 0; kt <= qt; kt++) {
        __syncthreads();   // protect prev-iter KP/Vs reads + init
        int k0 = kt * 64;
        size_t baseK = ((size_t)(b * 1024 + k0)) * 2304 + 768 + h * 64;
        for (int e = tid; e < 1024; e += 256) {
            int c = e >> 4, dq = e & 15;
            float4 v = *(const float4*)(qkv + baseK + (size_t)c * 2304 + dq * 4);
            KP[(dq * 4 + 0) * ALDS + c] = v.x;
            KP[(dq * 4 + 1) * ALDS + c] = v.y;
            KP[(dq * 4 + 2) * ALDS + c] = v.z;
            KP[(dq * 4 + 3) * ALDS + c] = v.w;
            float4 w = *(const float4*)(qkv + baseK + 768 + (size_t)c * 2304 + dq * 4);
            *(float4*)&Vs[c * ALDS + dq * 4] = w;
        }
        __syncthreads();
        if (tid < 64) {
            float s = 0.f;
            for (int d = 0; d < 64; d++) { float v = KP[d * ALDS + tid]; s += v * v; }
            kn[tid] = s;
        }
        __syncthreads();

        // S = Q @ K^T  (KP is [d][c])
        float sacc[4][4] = {};
        #pragma unroll 8
        for (int d = 0; d < 64; d++) {
            float av[4], bv[4];
            #pragma unroll
            for (int i = 0; i < 4; i++) av[i] = Qs[(ty * 4 + i) * ALDS + d];
            #pragma unroll
            for (int j = 0; j < 4; j++) bv[j] = KP[d * ALDS + tx * 4 + j];
            #pragma unroll
            for (int i = 0; i < 4; i++)
                #pragma unroll
                for (int j = 0; j < 4; j++)
                    sacc[i][j] = fmaf(av[i], bv[j], sacc[i][j]);
        }

        // yat transform + causal mask + local row max
        float lmax[4] = {-3.0e38f, -3.0e38f, -3.0e38f, -3.0e38f};
        #pragma unroll
        for (int i = 0; i < 4; i++) {
            int r = ty * 4 + i;
            int gq = q0 + r;
            float qnr = qn[r];
            #pragma unroll
            for (int j = 0; j < 4; j++) {
                int c = tx * 4 + j;
                int gk = k0 + c;
                float ds = sacc[i][j] * isc;
                float dist = qnr + kn[c] - 2.f * ds + YAT_EPS;
                float val = ds * ds / dist;
                if (gk > gq) val = -3.0e38f;
                sacc[i][j] = val;
                lmax[i] = fmaxf(lmax[i], val);
            }
        }
        #pragma unroll
        for (int i = 0; i < 4; i++) red[(ty * 4 + i) * 17 + tx] = lmax[i];
        __syncthreads();                      // sync A
        if (tid < 64) {
            float mx = red[tid * 17];
            for (int t = 1; t < 16; t++) mx = fmaxf(mx, red[tid * 17 + t]);
            float mold = mrow[tid];
            float mnew = fmaxf(mold, mx);
            corr[tid] = __expf(mold - mnew);
            mrow[tid] = mnew;
        }
        __syncthreads();                      // sync B

        float lsum[4] = {};
        #pragma unroll
        for (int i = 0; i < 4; i++) {
            float m = mrow[ty * 4 + i];
            #pragma unroll
            for (int j = 0; j < 4; j++) {
                float p = __expf(sacc[i][j] - m);
                sacc[i][j] = p;
                lsum[i] += p;
            }
        }
        // P overwrites K buffer (K reads all done before sync A)
        #pragma unroll
        for (int i = 0; i < 4; i++) {
            #pragma unroll
            for (int j = 0; j < 4; j++)
                KP[(ty * 4 + i) * ALDS + tx * 4 + j] = sacc[i][j];
            red[(ty * 4 + i) * 17 + tx] = lsum[i];
        }
        __syncthreads();                      // sync C
        if (tid < 64) {
            float s = 0.f;
            for (int t = 0; t < 16; t++) s += red[tid * 17 + t];
            lrow[tid] = lrow[tid] * corr[tid] + s;
        }
        float cr[4];
        #pragma unroll
        for (int i = 0; i < 4; i++) cr[i] = corr[ty * 4 + i];
        #pragma unroll
        for (int i = 0; i < 4; i++)
            #pragma unroll
            for (int j = 0; j < 4; j++) o[i][j] *= cr[i];

        // O += P @ V
        #pragma unroll 4
        for (int kv = 0; kv < 64; kv++) {
            float av[4], bv[4];
            #pragma unroll
            for (int i = 0; i < 4; i++) av[i] = KP[(ty * 4 + i) * ALDS + kv];
            #pragma unroll
            for (int j = 0; j < 4; j++) bv[j] = Vs[kv * ALDS + tx * 4 + j];
            #pragma unroll
            for (int i = 0; i < 4; i++)
                #pragma unroll
                for (int j = 0; j < 4; j++)
                    o[i][j] = fmaf(av[i], bv[j], o[i][j]);
        }
    }
    __syncthreads();
    #pragma unroll
    for (int i = 0; i < 4; i++) {
        int r = ty * 4 + i;
        int gq = q0 + r;
        float inv_l = 1.f / lrow[r];
        #pragma unroll
        for (int j = 0; j < 4; j++)
            att[((size_t)(b * 1024 + gq)) * 768 + h * 64 + tx * 4 + j] = o[i][j] * inv_l;
    }
}

// ---------------- launch ------------------------------------------------------
extern "C" void kernel_launch(void* const* d_in, const int* in_sizes, int n_in,
                              void* d_out, int out_size) {
    const float* x          = (const float*)d_in[0];
    // d_in[1] = mask (causal tril, recomputed on device)
    const float* W_attn     = (const float*)d_in[2];
    const float* b_attn     = (const float*)d_in[3];
    const float* alpha_attn = (const float*)d_in[4];
    const float* W_proj     = (const float*)d_in[5];
    const float* b_proj     = (const float*)d_in[6];
    const float* alpha_proj = (const float*)d_in[7];
    float* out = (float*)d_out;

    float *qkv, *att, *xnorm, *onorm, *wn1, *wn2;
    cudaGetSymbolAddress((void**)&qkv,   g_qkv);
    cudaGetSymbolAddress((void**)&att,   g_att);
    cudaGetSymbolAddress((void**)&xnorm, g_xnorm);
    cudaGetSymbolAddress((void**)&onorm, g_onorm);
    cudaGetSymbolAddress((void**)&wn1,   g_wn1);
    cudaGetSymbolAddress((void**)&wn2,   g_wn2);

    const int M = 4096, C = 768, F1 = 2304;
    float base1 = sqrtf((float)F1) / log1pf((float)F1);
    float base2 = sqrtf((float)C)  / log1pf((float)C);

    // norms
    col_sqnorm<<<(F1 + 255) / 256, 256>>>(W_attn, wn1, C, F1);
    col_sqnorm<<<(C  + 255) / 256, 256>>>(W_proj, wn2, C, C);
    row_sqnorm<<<M, 256>>>(x, xnorm, C);

    // QKV = yat_dense(x, W_attn)
    yat_gemm<<<dim3(F1 / 64, M / 64), 256>>>(x, W_attn, xnorm, wn1, b_attn,
                                             alpha_attn, qkv, M, F1, C, base1);

    // attention
    static int smem_set = 0;
    int att_smem = (3 * 64 * ALDS + 5 * 64 + 64 * 17) * (int)sizeof(float);
    if (!smem_set) {
        cudaFuncSetAttribute(yat_attention,
                             cudaFuncAttributeMaxDynamicSharedMemorySize, att_smem);
        smem_set = 1;
    }
    yat_attention<<<dim3(16, 12, 4), 256, att_smem>>>(qkv, att);

    // proj = yat_dense(att, W_proj)
    row_sqnorm<<<M, 256>>>(att, onorm, C);
    yat_gemm<<<dim3(C / 64, M / 64), 256>>>(att, W_proj, onorm, wn2, b_proj,
                                            alpha_proj, out, M, C, C, base2);
}